// round 16
// baseline (speedup 1.0000x reference)
#include <cuda_runtime.h>

#define NN 100000
#define EE 800000
#define QUART_E 200000
#define INC 64
#define HH 128
#define KK 9
#define FULL 0xffffffffu

#define OFF_OUT 0
#define OFF_MC  1152
#define OFF_O   1153
#define OFF_S   1154
#define OFF_OA  901154

#define FMA2(acc, w, x2) \
    asm("fma.rn.f32x2 %0, %1, %2, %0;" : "+l"(acc) : "l"(w), "l"(x2))
#define PACKDUP(dst, f) \
    asm("mov.b64 %0, {%1, %1};" : "=l"(dst) : "r"(__float_as_uint(f)))
#define UNPACK2(lo, hi, v) do { unsigned _a, _b; \
    asm("mov.b64 {%0, %1}, %2;" : "=r"(_a), "=r"(_b) : "l"(v)); \
    lo = __uint_as_float(_a); hi = __uint_as_float(_b); } while (0)

// Scratch (static device globals — allocation-free).  All accumulators are
// zero-initialized at module load; k_zero (the LAST kernel in the pipeline)
// re-zeroes them for the next graph replay, so every call sees zeroed state.
// g_s12 pad lanes (9..11) are NEVER written non-zero: static init keeps them 0.
__device__ __align__(16) float g_xs[NN * INC];    // dinv[n] * x[n]
__device__ __align__(16) float g_aggx[NN * INC];  // xs[n] + sum xs[src]
__device__ __align__(16) float g_s12[NN * 12];    // s padded to 12 floats
__device__ __align__(16) float g_t[NN * 12];      // t[d] = sum_{e:dst=d} s[src]
__device__ float g_deg[NN];
__device__ float g_xpool[KK * HH];
__device__ float g_outadj[KK * KK];
__device__ float g_ss[KK * KK];
__device__ float g_den[1];

// ---------------------------------------------------------------------------
// Zero accumulators for the NEXT call (runs at pipeline tail).
// ---------------------------------------------------------------------------
__global__ void k_zero() {
    int i = blockIdx.x * blockDim.x + threadIdx.x;
    if (i < NN) g_deg[i] = 0.f;
    if (i < NN * 12) g_t[i] = 0.f;
    if (i < KK * HH) g_xpool[i] = 0.f;
    if (i < KK * KK) { g_outadj[i] = 0.f; g_ss[i] = 0.f; }
    if (i == 0) g_den[0] = 0.f;
}

// ---------------------------------------------------------------------------
// In-degree at dst (no self loops)
// ---------------------------------------------------------------------------
__global__ void k_deg(const int* __restrict__ dst) {
    int e = blockIdx.x * blockDim.x + threadIdx.x;
    if (e < EE) atomicAdd(&g_deg[dst[e]], 1.0f);
}

// ---------------------------------------------------------------------------
// xs = dinv[n]*x[n]; aggx seeded with xs (self-loop term). float4 per thread.
// ---------------------------------------------------------------------------
__global__ void k_scale(const float* __restrict__ x) {
    int i = blockIdx.x * blockDim.x + threadIdx.x;  // float4 index, 16 per row
    if (i >= NN * 16) return;
    int n = i >> 4;
    float di = rsqrtf(g_deg[n] + 1.0f);
    float4 v = reinterpret_cast<const float4*>(x)[i];
    v.x *= di; v.y *= di; v.z *= di; v.w *= di;
    reinterpret_cast<float4*>(g_xs)[i] = v;
    reinterpret_cast<float4*>(g_aggx)[i] = v;
}

// ---------------------------------------------------------------------------
// Edge scatter: aggx[dst] += xs[src].  16 lanes per edge QUAD (edges p,
// p+E/4, p+E/2, p+3E/4): four float4 gathers in flight before reductions.
// ---------------------------------------------------------------------------
__global__ void k_scatter(const int* __restrict__ src, const int* __restrict__ dst) {
    int gtid = blockIdx.x * blockDim.x + threadIdx.x;
    int p = gtid >> 4;
    if (p >= QUART_E) return;
    int l = gtid & 15;
    int s0 = __ldg(&src[p]),               d0 = __ldg(&dst[p]);
    int s1 = __ldg(&src[p + QUART_E]),     d1 = __ldg(&dst[p + QUART_E]);
    int s2 = __ldg(&src[p + 2 * QUART_E]), d2 = __ldg(&dst[p + 2 * QUART_E]);
    int s3 = __ldg(&src[p + 3 * QUART_E]), d3 = __ldg(&dst[p + 3 * QUART_E]);
    float4 v0 = __ldg(&reinterpret_cast<const float4*>(g_xs)[s0 * 16 + l]);
    float4 v1 = __ldg(&reinterpret_cast<const float4*>(g_xs)[s1 * 16 + l]);
    float4 v2 = __ldg(&reinterpret_cast<const float4*>(g_xs)[s2 * 16 + l]);
    float4 v3 = __ldg(&reinterpret_cast<const float4*>(g_xs)[s3 * 16 + l]);
    float* a0 = g_aggx + (size_t)d0 * INC + l * 4;
    float* a1 = g_aggx + (size_t)d1 * INC + l * 4;
    float* a2 = g_aggx + (size_t)d2 * INC + l * 4;
    float* a3 = g_aggx + (size_t)d3 * INC + l * 4;
    asm volatile("red.global.add.v4.f32 [%0], {%1, %2, %3, %4};"
                 :: "l"(a0), "f"(v0.x), "f"(v0.y), "f"(v0.z), "f"(v0.w) : "memory");
    asm volatile("red.global.add.v4.f32 [%0], {%1, %2, %3, %4};"
                 :: "l"(a1), "f"(v1.x), "f"(v1.y), "f"(v1.z), "f"(v1.w) : "memory");
    asm volatile("red.global.add.v4.f32 [%0], {%1, %2, %3, %4};"
                 :: "l"(a2), "f"(v2.x), "f"(v2.y), "f"(v2.z), "f"(v2.w) : "memory");
    asm volatile("red.global.add.v4.f32 [%0], {%1, %2, %3, %4};"
                 :: "l"(a3), "f"(v3.x), "f"(v3.y), "f"(v3.z), "f"(v3.w) : "memory");
}

// ---------------------------------------------------------------------------
// Fused: hx = relu((dinv*aggx)@W1 + b1); s = softmax(hx@Wp + bp);
// write s (+ s12 copy); accumulate x_pool, den.
// Warp processes 4 nodes/iter.  GEMM + logits use fma.rn.f32x2 with
// pre-duplicated xT pairs (pack once at staging, zero packs in k-loop).
// Bit-exact vs FFMA (f32x2 = two independent RN fp32 FMAs).
// __launch_bounds__(256, 2): cap at 128 regs so 2 blocks/SM fit.
// ---------------------------------------------------------------------------
__global__ void __launch_bounds__(256, 2) k_s(
        const float* __restrict__ W1, const float* __restrict__ b1,
        const float* __restrict__ Wp, const float* __restrict__ bp,
        float* __restrict__ sout) {
    __shared__ float Ws[INC * HH];     // 32 KB
    __shared__ float Wp12[HH * 12];    // Wp padded to 12 cols
    __shared__ float b1s[HH];
    __shared__ float bps[KK];
    __shared__ float xps[KK * HH];
    __shared__ __align__(16) unsigned long long xT2[8][INC * 4];  // {x,x} pairs
    for (int i = threadIdx.x; i < INC * HH; i += blockDim.x) Ws[i] = W1[i];
    for (int i = threadIdx.x; i < HH * 12; i += blockDim.x) {
        int r = i / 12, c = i % 12;
        Wp12[i] = (c < KK) ? Wp[r * KK + c] : 0.f;
    }
    for (int i = threadIdx.x; i < KK * HH; i += blockDim.x) xps[i] = 0.f;
    if (threadIdx.x < HH) b1s[threadIdx.x] = b1[threadIdx.x];
    if (threadIdx.x < KK) bps[threadIdx.x] = bp[threadIdx.x];
    __syncthreads();

    const int lane = threadIdx.x & 31, warp = threadIdx.x >> 5;
    const int gw = blockIdx.x * 8 + warp, nw = gridDim.x * 8;
    const int tn = lane & 3;    // node-in-group this lane stages
    const int tk = lane >> 2;   // k sub-offset (0..7)
    const ulonglong2* Ws8 = reinterpret_cast<const ulonglong2*>(Ws);
    const ulonglong2* Wp8 = reinterpret_cast<const ulonglong2*>(Wp12);
    const ulonglong2* xT28 = reinterpret_cast<const ulonglong2*>(xT2[warp]);

    float4 bl = reinterpret_cast<const float4*>(b1s)[lane];

    float acc[KK][4];
#pragma unroll
    for (int k = 0; k < KK; k++)
#pragma unroll
        for (int j = 0; j < 4; j++) acc[k][j] = 0.f;
    float dena = 0.f;

    for (int g = gw; g * 4 < NN; g += nw) {
        const int base = g * 4;
        // stage dinv-scaled x transposed + duplicated:
        // xT2[k*4+nn] = {x,x} where x = dinv[base+nn]*aggx[base+nn][k]
        float di = rsqrtf(g_deg[base + tn] + 1.0f);
        __syncwarp();
#pragma unroll
        for (int r = 0; r < 8; r++) {
            float xval = g_aggx[(size_t)(base + tn) * INC + r * 8 + tk] * di;
            unsigned long long xp;
            PACKDUP(xp, xval);
            xT2[warp][r * 32 + lane] = xp;   // index (r*8+tk)*4 + tn
        }
        __syncwarp();
        // GEMM: 4 nodes x 4 cols per lane over K=64; 8 FMA2 per step.
        unsigned long long ga01[4], ga23[4];
#pragma unroll
        for (int nn = 0; nn < 4; nn++) { ga01[nn] = 0ull; ga23[nn] = 0ull; }
#pragma unroll
        for (int k = 0; k < INC; k++) {
            ulonglong2 w2 = Ws8[k * 32 + lane];      // {w.x,w.y},{w.z,w.w}
            ulonglong2 x01 = xT28[k * 2];            // xx pairs nodes 0,1
            ulonglong2 x23 = xT28[k * 2 + 1];        // xx pairs nodes 2,3
            FMA2(ga01[0], w2.x, x01.x); FMA2(ga23[0], w2.y, x01.x);
            FMA2(ga01[1], w2.x, x01.y); FMA2(ga23[1], w2.y, x01.y);
            FMA2(ga01[2], w2.x, x23.x); FMA2(ga23[2], w2.y, x23.x);
            FMA2(ga01[3], w2.x, x23.y); FMA2(ga23[3], w2.y, x23.y);
        }
        // epilogue per node
#pragma unroll
        for (int nn = 0; nn < 4; nn++) {
            const int n = base + nn;
            float gx, gy, gz, gw_;
            UNPACK2(gx, gy, ga01[nn]);
            UNPACK2(gz, gw_, ga23[nn]);
            float v[4];
            v[0] = fmaxf(gx + bl.x, 0.f);
            v[1] = fmaxf(gy + bl.y, 0.f);
            v[2] = fmaxf(gz + bl.z, 0.f);
            v[3] = fmaxf(gw_ + bl.w, 0.f);

            // logits over 12 padded cols = 6 packed accumulators
            unsigned long long pp[6];
#pragma unroll
            for (int q = 0; q < 6; q++) pp[q] = 0ull;
#pragma unroll
            for (int j = 0; j < 4; j++) {
                unsigned long long v2;
                PACKDUP(v2, v[j]);
                const int r = (lane * 4 + j) * 3;
#pragma unroll
                for (int q = 0; q < 3; q++) {
                    ulonglong2 w = Wp8[r + q];
                    FMA2(pp[2 * q], w.x, v2);
                    FMA2(pp[2 * q + 1], w.y, v2);
                }
            }
            float p[10];
#pragma unroll
            for (int q = 0; q < 5; q++) UNPACK2(p[2 * q], p[2 * q + 1], pp[q]);
#pragma unroll
            for (int k = 0; k < KK; k++) {
                p[k] += __shfl_xor_sync(FULL, p[k], 16);
                p[k] += __shfl_xor_sync(FULL, p[k], 8);
                p[k] += __shfl_xor_sync(FULL, p[k], 4);
                p[k] += __shfl_xor_sync(FULL, p[k], 2);
                p[k] += __shfl_xor_sync(FULL, p[k], 1);
                p[k] += bps[k];
            }
            // softmax over K=9 (replicated in every lane)
            float m = p[0];
#pragma unroll
            for (int k = 1; k < KK; k++) m = fmaxf(m, p[k]);
            float sum = 0.f;
#pragma unroll
            for (int k = 0; k < KK; k++) { p[k] = __expf(p[k] - m); sum += p[k]; }
            float inv = 1.f / sum;
#pragma unroll
            for (int k = 0; k < KK; k++) p[k] *= inv;

            if (lane == 0) {
#pragma unroll
                for (int k = 0; k < KK; k++) {
                    sout[(size_t)n * KK + k] = p[k];
                    g_s12[(size_t)n * 12 + k] = p[k];
                }
                float s2 = 0.f;
#pragma unroll
                for (int k = 0; k < KK; k++) s2 += p[k] * p[k];
                dena += g_deg[n] * s2;
            }

#pragma unroll
            for (int k = 0; k < KK; k++) {
#pragma unroll
                for (int j = 0; j < 4; j++) acc[k][j] += p[k] * v[j];
            }
        }
    }

    if (lane == 0) atomicAdd(&g_den[0], dena);
#pragma unroll
    for (int k = 0; k < KK; k++)
#pragma unroll
        for (int j = 0; j < 4; j++)
            atomicAdd(&xps[k * HH + lane * 4 + j], acc[k][j]);
    __syncthreads();
    for (int i = threadIdx.x; i < KK * HH; i += blockDim.x)
        atomicAdd(&g_xpool[i], xps[i]);
}

// ---------------------------------------------------------------------------
// t[dst] += s12[src]: one thread per edge, 2x red.v4 + 1 scalar red (9 floats).
// ---------------------------------------------------------------------------
__global__ void k_tadd(const int* __restrict__ src, const int* __restrict__ dst) {
    int e = blockIdx.x * blockDim.x + threadIdx.x;
    if (e >= EE) return;
    int s = __ldg(&src[e]);
    int d = __ldg(&dst[e]);
    const float4* sp = reinterpret_cast<const float4*>(g_s12 + (size_t)s * 12);
    float4 v0 = __ldg(sp);
    float4 v1 = __ldg(sp + 1);
    float  v8 = __ldg(g_s12 + (size_t)s * 12 + 8);
    float* tp = g_t + (size_t)d * 12;
    asm volatile("red.global.add.v4.f32 [%0], {%1, %2, %3, %4};"
                 :: "l"(tp), "f"(v0.x), "f"(v0.y), "f"(v0.z), "f"(v0.w) : "memory");
    asm volatile("red.global.add.v4.f32 [%0], {%1, %2, %3, %4};"
                 :: "l"(tp + 4), "f"(v1.x), "f"(v1.y), "f"(v1.z), "f"(v1.w) : "memory");
    asm volatile("red.global.add.f32 [%0], %1;"
                 :: "l"(tp + 8), "f"(v8) : "memory");
}

// ---------------------------------------------------------------------------
// out_adj[k][l] = sum_n t[n][k]*s[n][l];  ss[k][l] = sum_n s[n][k]*s[n][l].
// Warp per node QUAD (4-deep gather ILP).  ALL shuffles unconditional (FULL
// mask); only the *2-indexed accumulates are guarded.
// ---------------------------------------------------------------------------
__global__ void k_outer() {
    const int lane = threadIdx.x & 31, warp = threadIdx.x >> 5;
    const int gw = blockIdx.x * 8 + warp, nw = gridDim.x * 8;
    const int i1 = lane + 32, i2 = lane + 64;
    const int k0 = lane / 9, l0 = lane % 9;
    const int k1 = i1 / 9, l1 = i1 % 9;
    const int k2 = (i2 < 81) ? (i2 / 9) : 0, l2 = (i2 < 81) ? (i2 % 9) : 0;
    float a0 = 0.f, a1 = 0.f, a2 = 0.f;
    float q0 = 0.f, q1 = 0.f, q2 = 0.f;
    for (int g = gw; g * 4 < NN; g += nw) {
        const int base = g * 4;
        float val[4];
#pragma unroll
        for (int u = 0; u < 4; u++) {
            float vv = 0.f;
            if (lane < 9)       vv = g_t[(size_t)(base + u) * 12 + lane];
            else if (lane < 18) vv = g_s12[(size_t)(base + u) * 12 + (lane - 9)];
            val[u] = vv;
        }
#pragma unroll
        for (int u = 0; u < 4; u++) {
            float x0 = __shfl_sync(FULL, val[u], k0), y0 = __shfl_sync(FULL, val[u], 9 + l0);
            float x1 = __shfl_sync(FULL, val[u], k1), y1 = __shfl_sync(FULL, val[u], 9 + l1);
            float x2 = __shfl_sync(FULL, val[u], k2), y2 = __shfl_sync(FULL, val[u], 9 + l2);
            float u0 = __shfl_sync(FULL, val[u], 9 + k0);
            float u1 = __shfl_sync(FULL, val[u], 9 + k1);
            float u2 = __shfl_sync(FULL, val[u], 9 + k2);
            a0 += x0 * y0; a1 += x1 * y1;
            q0 += u0 * y0; q1 += u1 * y1;
            if (i2 < 81) { a2 += x2 * y2; q2 += u2 * y2; }
        }
    }
    atomicAdd(&g_outadj[lane], a0);
    atomicAdd(&g_outadj[i1], a1);
    if (i2 < 81) atomicAdd(&g_outadj[i2], a2);
    atomicAdd(&g_ss[lane], q0);
    atomicAdd(&g_ss[i1], q1);
    if (i2 < 81) atomicAdd(&g_ss[i2], q2);
}

// ---------------------------------------------------------------------------
// Finalize: mc, o, normalized out_adj, log_softmax(x_pool). Single block.
// ---------------------------------------------------------------------------
__global__ void k_final(float* __restrict__ out) {
    __shared__ float oas[81], sss[81], dis[9];
    int t = threadIdx.x;
    if (t < 81) { oas[t] = g_outadj[t]; sss[t] = g_ss[t]; }
    __syncthreads();
    if (t == 0) {
        float tr = 0.f;
        for (int k = 0; k < KK; k++) tr += oas[k * KK + k];
        out[OFF_MC] = -(tr / (g_den[0] + 1e-15f));
        float n2 = 0.f;
        for (int i = 0; i < 81; i++) n2 += sss[i] * sss[i];
        float nf = sqrtf(n2);
        float o2 = 0.f;
        for (int k = 0; k < KK; k++)
            for (int l = 0; l < KK; l++) {
                float v = sss[k * KK + l] / nf - ((k == l) ? (1.f / 3.f) : 0.f);
                o2 += v * v;
            }
        out[OFF_O] = sqrtf(o2);
    }
    if (t < KK) {
        float dsum = 0.f;
        for (int l = 0; l < KK; l++)
            if (l != t) dsum += oas[t * KK + l];
        dis[t] = rsqrtf(dsum + 1e-15f);
    }
    __syncthreads();
    if (t < 81) {
        int k = t / KK, l = t % KK;
        out[OFF_OA + t] = (k == l) ? 0.f : dis[k] * oas[t] * dis[l];
    }
    // log_softmax over H per cluster row
    int lane = t & 31, warp = t >> 5;
    for (int k = warp; k < KK; k += 4) {
        float v[4], m = -1e30f;
#pragma unroll
        for (int j = 0; j < 4; j++) {
            v[j] = g_xpool[k * HH + lane + 32 * j];
            m = fmaxf(m, v[j]);
        }
        for (int off = 16; off > 0; off >>= 1) m = fmaxf(m, __shfl_xor_sync(FULL, m, off));
        float se = 0.f;
#pragma unroll
        for (int j = 0; j < 4; j++) se += expf(v[j] - m);
        for (int off = 16; off > 0; off >>= 1) se += __shfl_xor_sync(FULL, se, off);
        float lse = logf(se) + m;
#pragma unroll
        for (int j = 0; j < 4; j++) out[OFF_OUT + k * HH + lane + 32 * j] = v[j] - lse;
    }
}

// ---------------------------------------------------------------------------
extern "C" void kernel_launch(void* const* d_in, const int* in_sizes, int n_in,
                              void* d_out, int out_size) {
    const float* x  = (const float*)d_in[0];
    const int*   ei = (const int*)d_in[1];
    // d_in[2] = batch (all zeros, single graph) — unused
    const float* W1 = (const float*)d_in[3];
    const float* b1 = (const float*)d_in[4];
    const float* Wp = (const float*)d_in[5];
    const float* bp = (const float*)d_in[6];
    float* out = (float*)d_out;
    const int* src = ei;
    const int* dst = ei + EE;

    // Accumulators are zeroed: at process start by static init, thereafter by
    // the trailing k_zero of the previous call (graph replays are serial).
    k_deg<<<(EE + 255) / 256, 256>>>(dst);
    k_scale<<<(NN * 16 + 255) / 256, 256>>>(x);
    k_scatter<<<(QUART_E * 16) / 256, 256>>>(src, dst);
    k_s<<<592, 256>>>(W1, b1, Wp, bp, out + OFF_S);
    k_tadd<<<(EE + 255) / 256, 256>>>(src, dst);
    k_outer<<<592, 256>>>();
    k_final<<<1, 128>>>(out);
    k_zero<<<(NN * 12 + 255) / 256, 256>>>();
}

// round 17
// speedup vs baseline: 1.0292x; 1.0292x over previous
#include <cuda_runtime.h>

#define NN 100000
#define EE 800000
#define QUART_E 200000
#define HALF_E 400000
#define INC 64
#define HH 128
#define KK 9
#define FULL 0xffffffffu

#define OFF_OUT 0
#define OFF_MC  1152
#define OFF_O   1153
#define OFF_S   1154
#define OFF_OA  901154

// Scratch (static device globals — allocation-free).  All accumulators are
// zero-initialized at module load; k_zero (the LAST kernel in the pipeline)
// re-zeroes them for the next graph replay, so every call sees zeroed state.
// g_s12 pad lanes (9..11) are NEVER written non-zero: static init keeps them 0.
__device__ __align__(16) float g_xs[NN * INC];    // dinv[n] * x[n]
__device__ __align__(16) float g_aggx[NN * INC];  // xs[n] + sum xs[src]
__device__ __align__(16) float g_s12[NN * 12];    // s padded to 12 floats
__device__ __align__(16) float g_t[NN * 12];      // t[d] = sum_{e:dst=d} s[src]
__device__ float g_deg[NN];
__device__ float g_xpool[KK * HH];
__device__ float g_outadj[KK * KK];
__device__ float g_ss[KK * KK];
__device__ float g_den[1];

// ---------------------------------------------------------------------------
// Zero accumulators for the NEXT call (runs at pipeline tail).
// ---------------------------------------------------------------------------
__global__ void k_zero() {
    int i = blockIdx.x * blockDim.x + threadIdx.x;
    if (i < NN) g_deg[i] = 0.f;
    if (i < NN * 12) g_t[i] = 0.f;
    if (i < KK * HH) g_xpool[i] = 0.f;
    if (i < KK * KK) { g_outadj[i] = 0.f; g_ss[i] = 0.f; }
    if (i == 0) g_den[0] = 0.f;
}

// ---------------------------------------------------------------------------
// In-degree at dst (no self loops).  One thread per 4 edges (int4 load).
// EE % 4 == 0.
// ---------------------------------------------------------------------------
__global__ void k_deg(const int* __restrict__ dst) {
    int q = blockIdx.x * blockDim.x + threadIdx.x;
    if (q >= EE / 4) return;
    int4 d = __ldg(&reinterpret_cast<const int4*>(dst)[q]);
    atomicAdd(&g_deg[d.x], 1.0f);
    atomicAdd(&g_deg[d.y], 1.0f);
    atomicAdd(&g_deg[d.z], 1.0f);
    atomicAdd(&g_deg[d.w], 1.0f);
}

// ---------------------------------------------------------------------------
// xs = dinv[n]*x[n]; aggx seeded with xs (self-loop term). float4 per thread.
// ---------------------------------------------------------------------------
__global__ void k_scale(const float* __restrict__ x) {
    int i = blockIdx.x * blockDim.x + threadIdx.x;  // float4 index, 16 per row
    if (i >= NN * 16) return;
    int n = i >> 4;
    float di = rsqrtf(g_deg[n] + 1.0f);
    float4 v = reinterpret_cast<const float4*>(x)[i];
    v.x *= di; v.y *= di; v.z *= di; v.w *= di;
    reinterpret_cast<float4*>(g_xs)[i] = v;
    reinterpret_cast<float4*>(g_aggx)[i] = v;
}

// ---------------------------------------------------------------------------
// Edge scatter: aggx[dst] += xs[src].  16 lanes per edge QUAD (edges p,
// p+E/4, p+E/2, p+3E/4): four float4 gathers in flight before reductions.
// ---------------------------------------------------------------------------
__global__ void k_scatter(const int* __restrict__ src, const int* __restrict__ dst) {
    int gtid = blockIdx.x * blockDim.x + threadIdx.x;
    int p = gtid >> 4;
    if (p >= QUART_E) return;
    int l = gtid & 15;
    int s0 = __ldg(&src[p]),               d0 = __ldg(&dst[p]);
    int s1 = __ldg(&src[p + QUART_E]),     d1 = __ldg(&dst[p + QUART_E]);
    int s2 = __ldg(&src[p + 2 * QUART_E]), d2 = __ldg(&dst[p + 2 * QUART_E]);
    int s3 = __ldg(&src[p + 3 * QUART_E]), d3 = __ldg(&dst[p + 3 * QUART_E]);
    float4 v0 = __ldg(&reinterpret_cast<const float4*>(g_xs)[s0 * 16 + l]);
    float4 v1 = __ldg(&reinterpret_cast<const float4*>(g_xs)[s1 * 16 + l]);
    float4 v2 = __ldg(&reinterpret_cast<const float4*>(g_xs)[s2 * 16 + l]);
    float4 v3 = __ldg(&reinterpret_cast<const float4*>(g_xs)[s3 * 16 + l]);
    float* a0 = g_aggx + (size_t)d0 * INC + l * 4;
    float* a1 = g_aggx + (size_t)d1 * INC + l * 4;
    float* a2 = g_aggx + (size_t)d2 * INC + l * 4;
    float* a3 = g_aggx + (size_t)d3 * INC + l * 4;
    asm volatile("red.global.add.v4.f32 [%0], {%1, %2, %3, %4};"
                 :: "l"(a0), "f"(v0.x), "f"(v0.y), "f"(v0.z), "f"(v0.w) : "memory");
    asm volatile("red.global.add.v4.f32 [%0], {%1, %2, %3, %4};"
                 :: "l"(a1), "f"(v1.x), "f"(v1.y), "f"(v1.z), "f"(v1.w) : "memory");
    asm volatile("red.global.add.v4.f32 [%0], {%1, %2, %3, %4};"
                 :: "l"(a2), "f"(v2.x), "f"(v2.y), "f"(v2.z), "f"(v2.w) : "memory");
    asm volatile("red.global.add.v4.f32 [%0], {%1, %2, %3, %4};"
                 :: "l"(a3), "f"(v3.x), "f"(v3.y), "f"(v3.z), "f"(v3.w) : "memory");
}

// ---------------------------------------------------------------------------
// Fused: hx = relu((dinv*aggx)@W1 + b1); s = softmax(hx@Wp + bp);
// write s (+ s12 copy); accumulate x_pool, den.
// Warp processes 4 nodes/iter; shuffle-free GEMM via transposed smem staging.
// __launch_bounds__(256, 2): cap at 128 regs so 2 blocks/SM fit.
// (R14-proven float4 version; FMA2 variants blacklisted after R9/R16.)
// ---------------------------------------------------------------------------
__global__ void __launch_bounds__(256, 2) k_s(
        const float* __restrict__ W1, const float* __restrict__ b1,
        const float* __restrict__ Wp, const float* __restrict__ bp,
        float* __restrict__ sout) {
    __shared__ float Ws[INC * HH];     // 32 KB, read as float4
    __shared__ float Wp12[HH * 12];    // Wp padded to 12 cols
    __shared__ float b1s[HH];
    __shared__ float bps[KK];
    __shared__ float xps[KK * HH];
    __shared__ __align__(16) float xT[8][INC * 4];  // per-warp transposed x
    for (int i = threadIdx.x; i < INC * HH; i += blockDim.x) Ws[i] = W1[i];
    for (int i = threadIdx.x; i < HH * 12; i += blockDim.x) {
        int r = i / 12, c = i % 12;
        Wp12[i] = (c < KK) ? Wp[r * KK + c] : 0.f;
    }
    for (int i = threadIdx.x; i < KK * HH; i += blockDim.x) xps[i] = 0.f;
    if (threadIdx.x < HH) b1s[threadIdx.x] = b1[threadIdx.x];
    if (threadIdx.x < KK) bps[threadIdx.x] = bp[threadIdx.x];
    __syncthreads();

    const int lane = threadIdx.x & 31, warp = threadIdx.x >> 5;
    const int gw = blockIdx.x * 8 + warp, nw = gridDim.x * 8;
    const int tn = lane & 3;    // node-in-group this lane stages
    const int tk = lane >> 2;   // k sub-offset (0..7)
    const float4* Ws4 = reinterpret_cast<const float4*>(Ws);
    const float4* Wp4 = reinterpret_cast<const float4*>(Wp12);
    const float4* xT4 = reinterpret_cast<const float4*>(xT[warp]);

    float4 bl = reinterpret_cast<const float4*>(b1s)[lane];

    float acc[KK][4];
#pragma unroll
    for (int k = 0; k < KK; k++)
#pragma unroll
        for (int j = 0; j < 4; j++) acc[k][j] = 0.f;
    float dena = 0.f;

    for (int g = gw; g * 4 < NN; g += nw) {
        const int base = g * 4;
        // stage dinv-scaled x transposed: xT[k][nn] = dinv[base+nn]*aggx[base+nn][k]
        float di = rsqrtf(g_deg[base + tn] + 1.0f);
        __syncwarp();
#pragma unroll
        for (int r = 0; r < 8; r++) {
            float xval = g_aggx[(size_t)(base + tn) * INC + r * 8 + tk];
            xT[warp][r * 32 + lane] = xval * di;   // == xT[(r*8+tk)*4 + tn]
        }
        __syncwarp();
        // GEMM: 4 nodes x 4 cols per lane over K=64, shuffle-free
        float4 ga[4];
#pragma unroll
        for (int nn = 0; nn < 4; nn++) ga[nn] = make_float4(0.f, 0.f, 0.f, 0.f);
#pragma unroll
        for (int k = 0; k < INC; k++) {
            float4 w = Ws4[k * 32 + lane];
            float4 xx = xT4[k];
            ga[0].x += xx.x * w.x; ga[0].y += xx.x * w.y;
            ga[0].z += xx.x * w.z; ga[0].w += xx.x * w.w;
            ga[1].x += xx.y * w.x; ga[1].y += xx.y * w.y;
            ga[1].z += xx.y * w.z; ga[1].w += xx.y * w.w;
            ga[2].x += xx.z * w.x; ga[2].y += xx.z * w.y;
            ga[2].z += xx.z * w.z; ga[2].w += xx.z * w.w;
            ga[3].x += xx.w * w.x; ga[3].y += xx.w * w.y;
            ga[3].z += xx.w * w.z; ga[3].w += xx.w * w.w;
        }
        // epilogue per node
#pragma unroll
        for (int nn = 0; nn < 4; nn++) {
            const int n = base + nn;
            float v[4];
            v[0] = fmaxf(ga[nn].x + bl.x, 0.f);
            v[1] = fmaxf(ga[nn].y + bl.y, 0.f);
            v[2] = fmaxf(ga[nn].z + bl.z, 0.f);
            v[3] = fmaxf(ga[nn].w + bl.w, 0.f);

            float4 p4[3];
#pragma unroll
            for (int q = 0; q < 3; q++) p4[q] = make_float4(0.f, 0.f, 0.f, 0.f);
#pragma unroll
            for (int j = 0; j < 4; j++) {
                const int r = (lane * 4 + j) * 3;
#pragma unroll
                for (int q = 0; q < 3; q++) {
                    float4 w = Wp4[r + q];
                    p4[q].x += v[j] * w.x; p4[q].y += v[j] * w.y;
                    p4[q].z += v[j] * w.z; p4[q].w += v[j] * w.w;
                }
            }
            float p[KK] = {p4[0].x, p4[0].y, p4[0].z, p4[0].w,
                           p4[1].x, p4[1].y, p4[1].z, p4[1].w, p4[2].x};
#pragma unroll
            for (int k = 0; k < KK; k++) {
                p[k] += __shfl_xor_sync(FULL, p[k], 16);
                p[k] += __shfl_xor_sync(FULL, p[k], 8);
                p[k] += __shfl_xor_sync(FULL, p[k], 4);
                p[k] += __shfl_xor_sync(FULL, p[k], 2);
                p[k] += __shfl_xor_sync(FULL, p[k], 1);
                p[k] += bps[k];
            }
            // softmax over K=9 (replicated in every lane)
            float m = p[0];
#pragma unroll
            for (int k = 1; k < KK; k++) m = fmaxf(m, p[k]);
            float sum = 0.f;
#pragma unroll
            for (int k = 0; k < KK; k++) { p[k] = __expf(p[k] - m); sum += p[k]; }
            float inv = 1.f / sum;
#pragma unroll
            for (int k = 0; k < KK; k++) p[k] *= inv;

            if (lane == 0) {
#pragma unroll
                for (int k = 0; k < KK; k++) {
                    sout[(size_t)n * KK + k] = p[k];
                    g_s12[(size_t)n * 12 + k] = p[k];
                }
                float s2 = 0.f;
#pragma unroll
                for (int k = 0; k < KK; k++) s2 += p[k] * p[k];
                dena += g_deg[n] * s2;
            }

#pragma unroll
            for (int k = 0; k < KK; k++) {
#pragma unroll
                for (int j = 0; j < 4; j++) acc[k][j] += p[k] * v[j];
            }
        }
    }

    if (lane == 0) atomicAdd(&g_den[0], dena);
#pragma unroll
    for (int k = 0; k < KK; k++)
#pragma unroll
        for (int j = 0; j < 4; j++)
            atomicAdd(&xps[k * HH + lane * 4 + j], acc[k][j]);
    __syncthreads();
    for (int i = threadIdx.x; i < KK * HH; i += blockDim.x)
        atomicAdd(&g_xpool[i], xps[i]);
}

// ---------------------------------------------------------------------------
// t[dst] += s12[src]: one thread per edge PAIR (e, e+E/2); both 12-float
// gathers in flight before the six reductions.
// ---------------------------------------------------------------------------
__global__ void k_tadd(const int* __restrict__ src, const int* __restrict__ dst) {
    int e = blockIdx.x * blockDim.x + threadIdx.x;
    if (e >= HALF_E) return;
    int s0 = __ldg(&src[e]),          d0 = __ldg(&dst[e]);
    int s1 = __ldg(&src[e + HALF_E]), d1 = __ldg(&dst[e + HALF_E]);
    const float4* sp0 = reinterpret_cast<const float4*>(g_s12 + (size_t)s0 * 12);
    const float4* sp1 = reinterpret_cast<const float4*>(g_s12 + (size_t)s1 * 12);
    float4 a0 = __ldg(sp0);
    float4 a1 = __ldg(sp0 + 1);
    float  a8 = __ldg(g_s12 + (size_t)s0 * 12 + 8);
    float4 b0 = __ldg(sp1);
    float4 b1 = __ldg(sp1 + 1);
    float  b8 = __ldg(g_s12 + (size_t)s1 * 12 + 8);
    float* t0 = g_t + (size_t)d0 * 12;
    float* t1 = g_t + (size_t)d1 * 12;
    asm volatile("red.global.add.v4.f32 [%0], {%1, %2, %3, %4};"
                 :: "l"(t0), "f"(a0.x), "f"(a0.y), "f"(a0.z), "f"(a0.w) : "memory");
    asm volatile("red.global.add.v4.f32 [%0], {%1, %2, %3, %4};"
                 :: "l"(t0 + 4), "f"(a1.x), "f"(a1.y), "f"(a1.z), "f"(a1.w) : "memory");
    asm volatile("red.global.add.f32 [%0], %1;" :: "l"(t0 + 8), "f"(a8) : "memory");
    asm volatile("red.global.add.v4.f32 [%0], {%1, %2, %3, %4};"
                 :: "l"(t1), "f"(b0.x), "f"(b0.y), "f"(b0.z), "f"(b0.w) : "memory");
    asm volatile("red.global.add.v4.f32 [%0], {%1, %2, %3, %4};"
                 :: "l"(t1 + 4), "f"(b1.x), "f"(b1.y), "f"(b1.z), "f"(b1.w) : "memory");
    asm volatile("red.global.add.f32 [%0], %1;" :: "l"(t1 + 8), "f"(b8) : "memory");
}

// ---------------------------------------------------------------------------
// out_adj[k][l] = sum_n t[n][k]*s[n][l];  ss[k][l] = sum_n s[n][k]*s[n][l].
// Warp per node QUAD (4-deep gather ILP).  ALL shuffles unconditional (FULL
// mask); only the *2-indexed accumulates are guarded.
// ---------------------------------------------------------------------------
__global__ void k_outer() {
    const int lane = threadIdx.x & 31, warp = threadIdx.x >> 5;
    const int gw = blockIdx.x * 8 + warp, nw = gridDim.x * 8;
    const int i1 = lane + 32, i2 = lane + 64;
    const int k0 = lane / 9, l0 = lane % 9;
    const int k1 = i1 / 9, l1 = i1 % 9;
    const int k2 = (i2 < 81) ? (i2 / 9) : 0, l2 = (i2 < 81) ? (i2 % 9) : 0;
    float a0 = 0.f, a1 = 0.f, a2 = 0.f;
    float q0 = 0.f, q1 = 0.f, q2 = 0.f;
    for (int g = gw; g * 4 < NN; g += nw) {
        const int base = g * 4;
        float val[4];
#pragma unroll
        for (int u = 0; u < 4; u++) {
            float vv = 0.f;
            if (lane < 9)       vv = g_t[(size_t)(base + u) * 12 + lane];
            else if (lane < 18) vv = g_s12[(size_t)(base + u) * 12 + (lane - 9)];
            val[u] = vv;
        }
#pragma unroll
        for (int u = 0; u < 4; u++) {
            float x0 = __shfl_sync(FULL, val[u], k0), y0 = __shfl_sync(FULL, val[u], 9 + l0);
            float x1 = __shfl_sync(FULL, val[u], k1), y1 = __shfl_sync(FULL, val[u], 9 + l1);
            float x2 = __shfl_sync(FULL, val[u], k2), y2 = __shfl_sync(FULL, val[u], 9 + l2);
            float u0 = __shfl_sync(FULL, val[u], 9 + k0);
            float u1 = __shfl_sync(FULL, val[u], 9 + k1);
            float u2 = __shfl_sync(FULL, val[u], 9 + k2);
            a0 += x0 * y0; a1 += x1 * y1;
            q0 += u0 * y0; q1 += u1 * y1;
            if (i2 < 81) { a2 += x2 * y2; q2 += u2 * y2; }
        }
    }
    atomicAdd(&g_outadj[lane], a0);
    atomicAdd(&g_outadj[i1], a1);
    if (i2 < 81) atomicAdd(&g_outadj[i2], a2);
    atomicAdd(&g_ss[lane], q0);
    atomicAdd(&g_ss[i1], q1);
    if (i2 < 81) atomicAdd(&g_ss[i2], q2);
}

// ---------------------------------------------------------------------------
// Finalize: mc, o, normalized out_adj, log_softmax(x_pool). Single block.
// ---------------------------------------------------------------------------
__global__ void k_final(float* __restrict__ out) {
    __shared__ float oas[81], sss[81], dis[9];
    int t = threadIdx.x;
    if (t < 81) { oas[t] = g_outadj[t]; sss[t] = g_ss[t]; }
    __syncthreads();
    if (t == 0) {
        float tr = 0.f;
        for (int k = 0; k < KK; k++) tr += oas[k * KK + k];
        out[OFF_MC] = -(tr / (g_den[0] + 1e-15f));
        float n2 = 0.f;
        for (int i = 0; i < 81; i++) n2 += sss[i] * sss[i];
        float nf = sqrtf(n2);
        float o2 = 0.f;
        for (int k = 0; k < KK; k++)
            for (int l = 0; l < KK; l++) {
                float v = sss[k * KK + l] / nf - ((k == l) ? (1.f / 3.f) : 0.f);
                o2 += v * v;
            }
        out[OFF_O] = sqrtf(o2);
    }
    if (t < KK) {
        float dsum = 0.f;
        for (int l = 0; l < KK; l++)
            if (l != t) dsum += oas[t * KK + l];
        dis[t] = rsqrtf(dsum + 1e-15f);
    }
    __syncthreads();
    if (t < 81) {
        int k = t / KK, l = t % KK;
        out[OFF_OA + t] = (k == l) ? 0.f : dis[k] * oas[t] * dis[l];
    }
    // log_softmax over H per cluster row
    int lane = t & 31, warp = t >> 5;
    for (int k = warp; k < KK; k += 4) {
        float v[4], m = -1e30f;
#pragma unroll
        for (int j = 0; j < 4; j++) {
            v[j] = g_xpool[k * HH + lane + 32 * j];
            m = fmaxf(m, v[j]);
        }
        for (int off = 16; off > 0; off >>= 1) m = fmaxf(m, __shfl_xor_sync(FULL, m, off));
        float se = 0.f;
#pragma unroll
        for (int j = 0; j < 4; j++) se += expf(v[j] - m);
        for (int off = 16; off > 0; off >>= 1) se += __shfl_xor_sync(FULL, se, off);
        float lse = logf(se) + m;
#pragma unroll
        for (int j = 0; j < 4; j++) out[OFF_OUT + k * HH + lane + 32 * j] = v[j] - lse;
    }
}

// ---------------------------------------------------------------------------
extern "C" void kernel_launch(void* const* d_in, const int* in_sizes, int n_in,
                              void* d_out, int out_size) {
    const float* x  = (const float*)d_in[0];
    const int*   ei = (const int*)d_in[1];
    // d_in[2] = batch (all zeros, single graph) — unused
    const float* W1 = (const float*)d_in[3];
    const float* b1 = (const float*)d_in[4];
    const float* Wp = (const float*)d_in[5];
    const float* bp = (const float*)d_in[6];
    float* out = (float*)d_out;
    const int* src = ei;
    const int* dst = ei + EE;

    // Accumulators are zeroed: at process start by static init, thereafter by
    // the trailing k_zero of the previous call (graph replays are serial).
    k_deg<<<(EE / 4 + 255) / 256, 256>>>(dst);
    k_scale<<<(NN * 16 + 255) / 256, 256>>>(x);
    k_scatter<<<(QUART_E * 16) / 256, 256>>>(src, dst);
    k_s<<<592, 256>>>(W1, b1, Wp, bp, out + OFF_S);
    k_tadd<<<(HALF_E + 255) / 256, 256>>>(src, dst);
    k_outer<<<592, 256>>>();
    k_final<<<1, 128>>>(out);
    k_zero<<<(NN * 12 + 255) / 256, 256>>>();
}